// round 1
// baseline (speedup 1.0000x reference)
#include <cuda_runtime.h>

#define SPX 3136      // 56*56
#define BATCH 8
#define DIM 256
#define DIM2 512

// Scratch (allocation-free rule: static __device__ arrays)
__device__ float g_hcat[(size_t)BATCH * DIM2 * SPX];  // [B, 512, S]: ch 0..255 = h, 256..511 = xj
__device__ float g_gbuf[(size_t)BATCH * DIM2 * SPX];  // [B, 512, S]: gelu output
__device__ float g_sc1[DIM], g_sh1[DIM];
__device__ float g_scg[DIM2], g_shg[DIM2];
__device__ float g_sc2[DIM], g_sh2[DIM];

// ---------------------------------------------------------------------------
// Fold conv-bias + BN into per-channel scale/shift:
// bn(conv + b) = conv*s + ((b - m)*s + be),  s = g/sqrt(v+eps)
// ---------------------------------------------------------------------------
__global__ void prep_kernel(const float* __restrict__ b1, const float* __restrict__ g1,
                            const float* __restrict__ be1, const float* __restrict__ m1,
                            const float* __restrict__ v1,
                            const float* __restrict__ bg, const float* __restrict__ gg,
                            const float* __restrict__ beg, const float* __restrict__ mg,
                            const float* __restrict__ vg,
                            const float* __restrict__ b2, const float* __restrict__ g2,
                            const float* __restrict__ be2, const float* __restrict__ m2,
                            const float* __restrict__ v2) {
    int i = threadIdx.x;  // 512 threads
    if (i < DIM) {
        float s = g1[i] / sqrtf(v1[i] + 1e-5f);
        g_sc1[i] = s;
        g_sh1[i] = (b1[i] - m1[i]) * s + be1[i];
        float s2 = g2[i] / sqrtf(v2[i] + 1e-5f);
        g_sc2[i] = s2;
        g_sh2[i] = (b2[i] - m2[i]) * s2 + be2[i];
    }
    float sg = gg[i] / sqrtf(vg[i] + 1e-5f);
    g_scg[i] = sg;
    g_shg[i] = (bg[i] - mg[i]) * sg + beg[i];
}

// ---------------------------------------------------------------------------
// Tiled fp32 GEMM using packed fma.rn.f32x2 (sm_100+/sm_103a).
//   dst[b, m, s] = epilogue( sum_k W[m,k] * src[b, k, s] )
// Block tile 128(M) x 128(N), BK=16, 256 threads, 8x8 per thread.
// N = 25088 = 196*128 exactly; M,K multiples of 128/16 -> no predication.
// MODE: 0 = scale/shift, 1 = scale/shift + exact GELU, 2 = scale/shift + residual
// ---------------------------------------------------------------------------
template <int MODE>
__global__ void __launch_bounds__(256, 2)
gemm_kernel(const float* __restrict__ W,     // [M, K] row-major
            const float* __restrict__ src,   // [B, K, SPX]
            float* __restrict__ dst,         // [B, dstC, SPX] (writes rows [0,M))
            const float* __restrict__ scale,
            const float* __restrict__ shift,
            const float* __restrict__ resid, // [B, M, SPX] or nullptr
            int M, int K, int dstC) {
    __shared__ float As[16][128];  // transposed: As[k][m]
    __shared__ float Bs[16][128];  // Bs[k][n]

    const int tid = threadIdx.x;
    const int n0 = blockIdx.x * 128;
    const int m0 = blockIdx.y * 128;

    // B-tile load mapping: thread -> float4 column (t%32), k-row (t/32, +8)
    const int fcol = tid & 31;
    const int brow = tid >> 5;
    const int nn = n0 + fcol * 4;
    const int bb = nn / SPX;        // batch boundaries are multiples of 4: float4-safe
    const int ss = nn - bb * SPX;
    const float* srcBase = src + (size_t)bb * K * SPX + ss;

    const int rowb = (tid >> 4) << 3;  // 0..120
    const int colb = (tid & 15) << 3;  // 0..120

    unsigned long long acc[8][4];
#pragma unroll
    for (int m = 0; m < 8; m++)
#pragma unroll
        for (int j = 0; j < 4; j++) acc[m][j] = 0ull;

    for (int k0 = 0; k0 < K; k0 += 16) {
        // Load A tile (128 x 16), store transposed into smem
#pragma unroll
        for (int r = 0; r < 2; r++) {
            int idx = tid + r * 256;        // 0..511
            int arow = idx >> 2;            // 0..127
            int kv = (idx & 3) << 2;        // 0,4,8,12
            float4 a4 = *(const float4*)(W + (size_t)(m0 + arow) * K + k0 + kv);
            As[kv + 0][arow] = a4.x;
            As[kv + 1][arow] = a4.y;
            As[kv + 2][arow] = a4.z;
            As[kv + 3][arow] = a4.w;
        }
        // Load B tile (16 x 128)
#pragma unroll
        for (int r = 0; r < 2; r++) {
            int kr = brow + r * 8;
            *(float4*)&Bs[kr][fcol * 4] =
                *(const float4*)(srcBase + (size_t)(k0 + kr) * SPX);
        }
        __syncthreads();

#pragma unroll
        for (int k = 0; k < 16; k++) {
            float4 a0 = *(const float4*)&As[k][rowb];
            float4 a1 = *(const float4*)&As[k][rowb + 4];
            float a[8] = {a0.x, a0.y, a0.z, a0.w, a1.x, a1.y, a1.z, a1.w};
            ulonglong2 q0 = *(const ulonglong2*)&Bs[k][colb];
            ulonglong2 q1 = *(const ulonglong2*)&Bs[k][colb + 4];
            unsigned long long bp[4] = {q0.x, q0.y, q1.x, q1.y};
#pragma unroll
            for (int m = 0; m < 8; m++) {
                unsigned long long ad;
                asm("mov.b64 %0, {%1, %1};" : "=l"(ad) : "f"(a[m]));
#pragma unroll
                for (int j = 0; j < 4; j++)
                    asm("fma.rn.f32x2 %0, %1, %2, %0;"
                        : "+l"(acc[m][j])
                        : "l"(ad), "l"(bp[j]));
            }
        }
        __syncthreads();
    }

    // Epilogue
    const int n = n0 + colb;   // multiple of 8; batch boundary multiple of 3136 (div by 8)
    const int b_ = n / SPX;
    const int s_ = n - b_ * SPX;

#pragma unroll
    for (int m = 0; m < 8; m++) {
        int gm = m0 + rowb + m;
        float sc = scale[gm];
        float sh = shift[gm];
        float v[8];
#pragma unroll
        for (int j = 0; j < 4; j++) {
            float lo, hi;
            asm("mov.b64 {%0, %1}, %2;" : "=f"(lo), "=f"(hi) : "l"(acc[m][j]));
            v[2 * j] = fmaf(lo, sc, sh);
            v[2 * j + 1] = fmaf(hi, sc, sh);
        }
        if (MODE == 1) {
#pragma unroll
            for (int j = 0; j < 8; j++)
                v[j] = 0.5f * v[j] * (1.0f + erff(v[j] * 0.70710678118654752f));
        }
        float* dp = dst + ((size_t)b_ * dstC + gm) * SPX + s_;
        if (MODE == 2) {
            const float* rp = resid + ((size_t)b_ * M + gm) * SPX + s_;
            float4 r0 = *(const float4*)rp;
            float4 r1 = *(const float4*)(rp + 4);
            v[0] += r0.x; v[1] += r0.y; v[2] += r0.z; v[3] += r0.w;
            v[4] += r1.x; v[5] += r1.y; v[6] += r1.z; v[7] += r1.w;
        }
        *(float4*)dp = make_float4(v[0], v[1], v[2], v[3]);
        *(float4*)(dp + 4) = make_float4(v[4], v[5], v[6], v[7]);
    }
}

// ---------------------------------------------------------------------------
// MRConv4d reduction. For each (b,c) 56x56 image:
// max_{i in {2,4,..,54}} (h - roll(h,i,axis)) over both axes, max'd with 0
//   == max(0, h - min(same-parity-col min excl self, same-parity-row min excl self))
// Two-smallest per parity class gives exact exclude-self min (ties handled).
// Reads g_hcat ch [0,256), writes ch [256,512).
// ---------------------------------------------------------------------------
__global__ void __launch_bounds__(256) mrconv_kernel() {
    const int bc = blockIdx.x;      // 0..2047
    const int b_ = bc >> 8;
    const int c_ = bc & 255;
    const float* h = g_hcat + ((size_t)b_ * DIM2 + c_) * SPX;
    float* out = g_hcat + ((size_t)b_ * DIM2 + c_ + DIM) * SPX;

    __shared__ float img[SPX];
    __shared__ float cm1[2][56], cm2[2][56];  // [parity][x]
    __shared__ float rm1[56][2], rm2[56][2];  // [y][parity]

    const int tid = threadIdx.x;
    for (int i = tid; i < SPX; i += 256) img[i] = h[i];
    __syncthreads();

    if (tid < 112) {                // column mins: (x, parity of y)
        int x = tid >> 1, p = tid & 1;
        float a1 = 1e30f, a2 = 1e30f;
        for (int y = p; y < 56; y += 2) {
            float v = img[y * 56 + x];
            if (v < a1) { a2 = a1; a1 = v; }
            else if (v < a2) { a2 = v; }
        }
        cm1[p][x] = a1; cm2[p][x] = a2;
    } else if (tid < 224) {         // row mins: (y, parity of x)
        int t = tid - 112;
        int y = t >> 1, p = t & 1;
        float a1 = 1e30f, a2 = 1e30f;
        for (int x = p; x < 56; x += 2) {
            float v = img[y * 56 + x];
            if (v < a1) { a2 = a1; a1 = v; }
            else if (v < a2) { a2 = v; }
        }
        rm1[y][p] = a1; rm2[y][p] = a2;
    }
    __syncthreads();

    for (int i = tid; i < SPX; i += 256) {
        int y = i / 56;
        int x = i - y * 56;
        float v = img[i];
        float ec = (v == cm1[y & 1][x]) ? cm2[y & 1][x] : cm1[y & 1][x];
        float er = (v == rm1[y][x & 1]) ? rm2[y][x & 1] : rm1[y][x & 1];
        out[i] = fmaxf(0.0f, v - fminf(ec, er));
    }
}

// ---------------------------------------------------------------------------
extern "C" void kernel_launch(void* const* d_in, const int* in_sizes, int n_in,
                              void* d_out, int out_size) {
    const float* x   = (const float*)d_in[0];
    const float* w1  = (const float*)d_in[1];
    const float* b1  = (const float*)d_in[2];
    const float* g1  = (const float*)d_in[3];
    const float* be1 = (const float*)d_in[4];
    const float* m1  = (const float*)d_in[5];
    const float* v1  = (const float*)d_in[6];
    const float* wg  = (const float*)d_in[7];
    const float* bg  = (const float*)d_in[8];
    const float* gg  = (const float*)d_in[9];
    const float* beg = (const float*)d_in[10];
    const float* mg  = (const float*)d_in[11];
    const float* vg  = (const float*)d_in[12];
    const float* w2  = (const float*)d_in[13];
    const float* b2  = (const float*)d_in[14];
    const float* g2  = (const float*)d_in[15];
    const float* be2 = (const float*)d_in[16];
    const float* m2  = (const float*)d_in[17];
    const float* v2  = (const float*)d_in[18];

    float *hcat, *gbuf, *sc1, *sh1, *scg, *shg, *sc2, *sh2;
    cudaGetSymbolAddress((void**)&hcat, g_hcat);
    cudaGetSymbolAddress((void**)&gbuf, g_gbuf);
    cudaGetSymbolAddress((void**)&sc1, g_sc1);
    cudaGetSymbolAddress((void**)&sh1, g_sh1);
    cudaGetSymbolAddress((void**)&scg, g_scg);
    cudaGetSymbolAddress((void**)&shg, g_shg);
    cudaGetSymbolAddress((void**)&sc2, g_sc2);
    cudaGetSymbolAddress((void**)&sh2, g_sh2);

    prep_kernel<<<1, 512>>>(b1, g1, be1, m1, v1, bg, gg, beg, mg, vg,
                            b2, g2, be2, m2, v2);

    // fc1: h = BN(x @ W1^T) -> hcat channels [0,256)
    gemm_kernel<0><<<dim3(196, 2), 256>>>(w1, x, hcat, sc1, sh1, nullptr,
                                          256, 256, 512);
    // MRConv4d: xj -> hcat channels [256,512)
    mrconv_kernel<<<2048, 256>>>();
    // grapher nn: g = GELU(BN(cat @ Wg^T))
    gemm_kernel<1><<<dim3(196, 4), 256>>>(wg, hcat, gbuf, scg, shg, nullptr,
                                          512, 512, 512);
    // fc2 + residual: out = BN(g @ W2^T) + x
    gemm_kernel<2><<<dim3(196, 2), 256>>>(w2, gbuf, (float*)d_out, sc2, sh2, x,
                                          256, 512, 256);
}

// round 3
// speedup vs baseline: 1.9541x; 1.9541x over previous
#include <cuda_runtime.h>
#include <cuda_bf16.h>
#include <cstdint>

#define SPX 3136      // 56*56
#define BATCH 8
#define DIM 256
#define DIM2 512
#define ROWS_TOT (BATCH * SPX)   // 25088 = 196 * 128

// ---------------- scratch (static __device__, allocation-free) ----------------
__device__ __nv_bfloat16 g_xTp[(size_t)ROWS_TOT * 3 * DIM];    // packed x: [B*S, 768]
__device__ __nv_bfloat16 g_catp[(size_t)ROWS_TOT * 3 * DIM2];  // packed cat: [B*S, 1536]
__device__ __nv_bfloat16 g_gp[(size_t)ROWS_TOT * 3 * DIM2];    // packed gelu out: [B*S, 1536]
__device__ float g_tmp2[(size_t)ROWS_TOT * DIM];               // fc2 out fp32 [B*S, 256]
__device__ __nv_bfloat16 g_w1p[(size_t)DIM * 3 * DIM];         // [256, 768]
__device__ __nv_bfloat16 g_wgp[(size_t)DIM2 * 3 * DIM2];       // [512, 1536]
__device__ __nv_bfloat16 g_w2p[(size_t)DIM * 3 * DIM2];        // [256, 1536]
__device__ float g_cm1[(size_t)BATCH * 56 * 2 * DIM], g_cm2[(size_t)BATCH * 56 * 2 * DIM];
__device__ float g_sc1[DIM], g_sh1[DIM];
__device__ float g_scg[DIM2], g_shg[DIM2];
__device__ float g_sc2[DIM], g_sh2[DIM];

// ---------------- PTX helpers (sm_80-generic only!) ----------------
__device__ __forceinline__ uint32_t smem_u32(const void* p) {
    uint32_t a;
    asm("{ .reg .u64 t; cvta.to.shared.u64 t, %1; cvt.u32.u64 %0, t; }" : "=r"(a) : "l"(p));
    return a;
}
#define CP_ASYNC16(sm, gm) \
    asm volatile("cp.async.cg.shared.global [%0], [%1], 16;" :: "r"(sm), "l"(gm) : "memory")
#define CP_COMMIT() asm volatile("cp.async.commit_group;" ::: "memory")
#define CP_WAIT1() asm volatile("cp.async.wait_group 1;" ::: "memory")
#define CP_WAIT0() asm volatile("cp.async.wait_group 0;" ::: "memory")
#define LDSM_X4(r0, r1, r2, r3, addr)                                        \
    asm volatile("ldmatrix.sync.aligned.m8n8.x4.shared.b16 {%0,%1,%2,%3}, [%4];" \
                 : "=r"(r0), "=r"(r1), "=r"(r2), "=r"(r3) : "r"(addr))

__device__ __forceinline__ void mma_bf16(float* d, const uint32_t* a, const uint32_t* b) {
    asm volatile(
        "mma.sync.aligned.m16n8k16.row.col.f32.bf16.bf16.f32 "
        "{%0,%1,%2,%3}, {%4,%5,%6,%7}, {%8,%9}, {%0,%1,%2,%3};"
        : "+f"(d[0]), "+f"(d[1]), "+f"(d[2]), "+f"(d[3])
        : "r"(a[0]), "r"(a[1]), "r"(a[2]), "r"(a[3]), "r"(b[0]), "r"(b[1]));
}

__device__ __forceinline__ void split2(float v, __nv_bfloat16& hi, __nv_bfloat16& lo) {
    hi = __float2bfloat16_rn(v);
    lo = __float2bfloat16_rn(v - __bfloat162float(hi));
}

// ---------------- prep: fold conv bias + BN ----------------
__global__ void prep_kernel(const float* __restrict__ b1, const float* __restrict__ g1,
                            const float* __restrict__ be1, const float* __restrict__ m1,
                            const float* __restrict__ v1,
                            const float* __restrict__ bg, const float* __restrict__ gg,
                            const float* __restrict__ beg, const float* __restrict__ mg,
                            const float* __restrict__ vg,
                            const float* __restrict__ b2, const float* __restrict__ g2,
                            const float* __restrict__ be2, const float* __restrict__ m2,
                            const float* __restrict__ v2) {
    int i = threadIdx.x;  // 512
    if (i < DIM) {
        float s = g1[i] / sqrtf(v1[i] + 1e-5f);
        g_sc1[i] = s; g_sh1[i] = (b1[i] - m1[i]) * s + be1[i];
        float s2 = g2[i] / sqrtf(v2[i] + 1e-5f);
        g_sc2[i] = s2; g_sh2[i] = (b2[i] - m2[i]) * s2 + be2[i];
    }
    float sg = gg[i] / sqrtf(vg[i] + 1e-5f);
    g_scg[i] = sg; g_shg[i] = (bg[i] - mg[i]) * sg + beg[i];
}

// ---------------- weight packing: W''[n, 3K] = [hiW | loW | hiW] ----------------
__global__ void pack_w(const float* __restrict__ W, __nv_bfloat16* __restrict__ Wp, int K) {
    int idx = blockIdx.x * 256 + threadIdx.x;
    int n = idx / K, k = idx - n * K;
    float v = W[idx];
    __nv_bfloat16 hi, lo;
    split2(v, hi, lo);
    __nv_bfloat16* row = Wp + (size_t)n * 3 * K;
    row[k] = hi; row[K + k] = lo; row[2 * K + k] = hi;
}

// ---------------- transpose x [B,256,S] -> packed [B*S, 768] = [hi | hi | lo] ----------------
__global__ void __launch_bounds__(256) transpose_in_pack(const float* __restrict__ x) {
    __shared__ float t[32][33];
    int tx = threadIdx.x & 31, ty = threadIdx.x >> 5;
    int s0 = blockIdx.x * 32, c0 = blockIdx.y * 32, b = blockIdx.z;
    const float* xp = x + ((size_t)b * DIM + c0) * SPX + s0;
    for (int i = ty; i < 32; i += 8) t[i][tx] = xp[(size_t)i * SPX + tx];
    __syncthreads();
    __nv_bfloat16* op = g_xTp + ((size_t)(b * SPX + s0)) * (3 * DIM) + c0;
    for (int i = ty; i < 32; i += 8) {
        float v = t[tx][i];
        __nv_bfloat16 hi, lo;
        split2(v, hi, lo);
        __nv_bfloat16* r = op + (size_t)i * (3 * DIM);
        r[tx] = hi; r[DIM + tx] = hi; r[2 * DIM + tx] = lo;
    }
}

// ---------------- out = tmp2^T + x ----------------
__global__ void __launch_bounds__(256) transpose_out_res(const float* __restrict__ x,
                                                         float* __restrict__ out) {
    __shared__ float t[32][33];
    int tx = threadIdx.x & 31, ty = threadIdx.x >> 5;
    int s0 = blockIdx.x * 32, c0 = blockIdx.y * 32, b = blockIdx.z;
    const float* ip = g_tmp2 + ((size_t)(b * SPX + s0)) * DIM + c0;
    for (int i = ty; i < 32; i += 8) t[i][tx] = ip[(size_t)i * DIM + tx];
    __syncthreads();
    size_t obase = ((size_t)b * DIM + c0) * SPX + s0;
    for (int i = ty; i < 32; i += 8)
        out[obase + (size_t)i * SPX + tx] = t[tx][i] + x[obase + (size_t)i * SPX + tx];
}

// ---------------- MRConv4d on packed cat [B*S, 1536] ----------------
// h[r,c] = catp[r, c] + catp[r, 1024+c]  (hi + lo), c in [0,256)
// xj = max(0, h - min(colMinExclSelf_sameParity, rowMinExclSelf_sameParity))
__global__ void __launch_bounds__(256) colmin_kernel() {
    int x = blockIdx.x, b = blockIdx.y, c = threadIdx.x;
    const __nv_bfloat16* base = g_catp + ((size_t)b * SPX) * 1536 + c;
    float a1e = 1e30f, a2e = 1e30f, a1o = 1e30f, a2o = 1e30f;
    for (int y = 0; y < 56; y += 2) {
        size_t p0 = (size_t)(y * 56 + x) * 1536;
        float v = __bfloat162float(base[p0]) + __bfloat162float(base[p0 + 1024]);
        if (v < a1e) { a2e = a1e; a1e = v; } else if (v < a2e) a2e = v;
        size_t p1 = (size_t)((y + 1) * 56 + x) * 1536;
        float w = __bfloat162float(base[p1]) + __bfloat162float(base[p1 + 1024]);
        if (w < a1o) { a2o = a1o; a1o = w; } else if (w < a2o) a2o = w;
    }
    size_t o = ((size_t)(b * 56 + x) * 2) * DIM + c;
    g_cm1[o] = a1e; g_cm2[o] = a2e;
    g_cm1[o + DIM] = a1o; g_cm2[o + DIM] = a2o;
}

__global__ void __launch_bounds__(256) row_combine_kernel() {
    int y = blockIdx.x, b = blockIdx.y, c = threadIdx.x;
    const __nv_bfloat16* base = g_catp + ((size_t)(b * SPX + y * 56)) * 1536 + c;
    float r1e = 1e30f, r2e = 1e30f, r1o = 1e30f, r2o = 1e30f;
    float hv[56];
    for (int x = 0; x < 56; x += 2) {
        size_t p0 = (size_t)x * 1536;
        float v = __bfloat162float(base[p0]) + __bfloat162float(base[p0 + 1024]);
        hv[x] = v;
        if (v < r1e) { r2e = r1e; r1e = v; } else if (v < r2e) r2e = v;
        size_t p1 = (size_t)(x + 1) * 1536;
        float w = __bfloat162float(base[p1]) + __bfloat162float(base[p1 + 1024]);
        hv[x + 1] = w;
        if (w < r1o) { r2o = r1o; r1o = w; } else if (w < r2o) r2o = w;
    }
    int py = y & 1;
    __nv_bfloat16* ob = g_catp + ((size_t)(b * SPX + y * 56)) * 1536 + c;
    for (int x = 0; x < 56; x++) {
        float v = hv[x];
        size_t o = ((size_t)(b * 56 + x) * 2 + py) * DIM + c;
        float c1 = g_cm1[o], c2 = g_cm2[o];
        float ec = (v == c1) ? c2 : c1;
        float m1r = (x & 1) ? r1o : r1e, m2r = (x & 1) ? r2o : r2e;
        float er = (v == m1r) ? m2r : m1r;
        float xj = fmaxf(0.0f, v - fminf(ec, er));
        __nv_bfloat16 hi, lo;
        split2(xj, hi, lo);
        __nv_bfloat16* r = ob + (size_t)x * 1536;
        r[256] = hi;        // hi(xj) in cat cols [256,512)
        r[768] = hi;        // dup hi
        r[1280] = lo;       // lo(xj)
    }
}

// ---------------- bf16 mma.sync GEMM ----------------
// D[r, n] = sum_k' A''[r0+r, k'] * W''[n0+n, k']   (K' = 3K packed)
// Tile 128x128, BK=64 (bf16), cp.async double buffer, 8 warps (2m x 4n), 64x32/warp.
// MODE 0: BN -> packed write [hi|hi|lo] stride 1536, offsets +512/+1024 (fc1, N=256)
// MODE 1: BN + GELU -> packed write stride 1536 (gemm2, N=512)
// MODE 2: BN -> fp32 write stride 256 (fc2)
#define GSMEM (65536 + 1024)
template <int MODE>
__global__ void __launch_bounds__(256, 2)
bf16_gemm(const __nv_bfloat16* __restrict__ Ag, const __nv_bfloat16* __restrict__ Wg,
          void* __restrict__ dstv,
          const float* __restrict__ scale, const float* __restrict__ shift, int Kp) {
    extern __shared__ __align__(1024) char smem[];
    const int tid = threadIdx.x, lane = tid & 31, wid = tid >> 5;
    const int warp_m = wid >> 2, warp_n = wid & 3;
    const int r0 = blockIdx.x * 128, n0 = blockIdx.y * 128;
    const uint32_t sb = smem_u32(smem);
    float* s_scale = (float*)(smem + 65536);
    float* s_shift = s_scale + 128;
    if (tid < 128) { s_scale[tid] = scale[n0 + tid]; s_shift[tid] = shift[n0 + tid]; }

    // loader offsets: idx = tid + i*256 -> row = idx>>3, chunk c = idx&7
    uint32_t loff[4];
    size_t aoff[4], boff[4];
#pragma unroll
    for (int i = 0; i < 4; i++) {
        int idx = tid + i * 256;
        int row = idx >> 3, c = idx & 7;
        loff[i] = row * 128 + ((c ^ (row & 7)) << 4);
        aoff[i] = (size_t)(r0 + row) * Kp + c * 8;
        boff[i] = (size_t)(n0 + row) * Kp + c * 8;
    }

    // ldmatrix row bases
    const int rowA[4] = {warp_m * 64 + 0 * 16 + (lane & 7) + ((lane >> 3) & 1) * 8,
                         warp_m * 64 + 1 * 16 + (lane & 7) + ((lane >> 3) & 1) * 8,
                         warp_m * 64 + 2 * 16 + (lane & 7) + ((lane >> 3) & 1) * 8,
                         warp_m * 64 + 3 * 16 + (lane & 7) + ((lane >> 3) & 1) * 8};
    const int kcA = lane >> 4;
    const int rowB[2] = {warp_n * 32 + 0 * 16 + (lane & 7) + ((lane >> 4) & 1) * 8,
                         warp_n * 32 + 1 * 16 + (lane & 7) + ((lane >> 4) & 1) * 8};
    const int kcB = (lane >> 3) & 1;

    float acc[4][4][4];
#pragma unroll
    for (int a = 0; a < 4; a++)
#pragma unroll
        for (int b = 0; b < 4; b++)
#pragma unroll
            for (int i = 0; i < 4; i++) acc[a][b][i] = 0.0f;

    const int NS = Kp >> 6;

    // prologue: load stage 0 into buf 0
#pragma unroll
    for (int i = 0; i < 4; i++) {
        CP_ASYNC16(sb + loff[i], Ag + aoff[i]);
        CP_ASYNC16(sb + 16384 + loff[i], Wg + boff[i]);
    }
    CP_COMMIT();

    for (int s = 0; s < NS; s++) {
        const int buf = s & 1;
        if (s + 1 < NS) {
            const uint32_t nb = sb + (buf ^ 1) * 32768;
            const size_t kadd = (size_t)(s + 1) * 64;
#pragma unroll
            for (int i = 0; i < 4; i++) {
                CP_ASYNC16(nb + loff[i], Ag + aoff[i] + kadd);
                CP_ASYNC16(nb + 16384 + loff[i], Wg + boff[i] + kadd);
            }
            CP_COMMIT();
            CP_WAIT1();
        } else {
            CP_WAIT0();
        }
        __syncthreads();

        const uint32_t aBase = sb + buf * 32768;
        const uint32_t bBase = aBase + 16384;
#pragma unroll
        for (int kk = 0; kk < 4; kk++) {
            uint32_t af[4][4];
#pragma unroll
            for (int mf = 0; mf < 4; mf++) {
                uint32_t addr = aBase + rowA[mf] * 128 +
                                (((kk * 2 + kcA) ^ (rowA[mf] & 7)) << 4);
                LDSM_X4(af[mf][0], af[mf][1], af[mf][2], af[mf][3], addr);
            }
            uint32_t bf[2][4];
#pragma unroll
            for (int nb2 = 0; nb2 < 2; nb2++) {
                uint32_t addr = bBase + rowB[nb2] * 128 +
                                (((kk * 2 + kcB) ^ (rowB[nb2] & 7)) << 4);
                LDSM_X4(bf[nb2][0], bf[nb2][1], bf[nb2][2], bf[nb2][3], addr);
            }
#pragma unroll
            for (int mf = 0; mf < 4; mf++)
#pragma unroll
                for (int nf = 0; nf < 4; nf++)
                    mma_bf16(acc[mf][nf], af[mf], &bf[nf >> 1][(nf & 1) * 2]);
        }
        __syncthreads();
    }

    // ---------------- epilogue ----------------
    const int mw = r0 + warp_m * 64;
    const int nw = warp_n * 32;  // local col within tile
#pragma unroll
    for (int mf = 0; mf < 4; mf++) {
#pragma unroll
        for (int nf = 0; nf < 4; nf++) {
#pragma unroll
            for (int half = 0; half < 2; half++) {
                int grow = mw + mf * 16 + (lane >> 2) + half * 8;
                int lcol = nw + nf * 8 + (lane & 3) * 2;
                float v0 = fmaf(acc[mf][nf][half * 2 + 0], s_scale[lcol], s_shift[lcol]);
                float v1 = fmaf(acc[mf][nf][half * 2 + 1], s_scale[lcol + 1], s_shift[lcol + 1]);
                if (MODE == 1) {
                    v0 = 0.5f * v0 * (1.0f + erff(v0 * 0.70710678118654752f));
                    v1 = 0.5f * v1 * (1.0f + erff(v1 * 0.70710678118654752f));
                }
                if (MODE == 2) {
                    float* dp = (float*)dstv + (size_t)grow * DIM + n0 + lcol;
                    *(float2*)dp = make_float2(v0, v1);
                } else {
                    __nv_bfloat16 h0, l0, h1, l1;
                    split2(v0, h0, l0);
                    split2(v1, h1, l1);
                    __nv_bfloat162 hp; hp.x = h0; hp.y = h1;
                    __nv_bfloat162 lp; lp.x = l0; lp.y = l1;
                    __nv_bfloat16* dp = (__nv_bfloat16*)dstv + (size_t)grow * 1536 + n0 + lcol;
                    *(__nv_bfloat162*)(dp) = hp;
                    *(__nv_bfloat162*)(dp + 512) = hp;
                    *(__nv_bfloat162*)(dp + 1024) = lp;
                }
            }
        }
    }
}

// ---------------------------------------------------------------------------
extern "C" void kernel_launch(void* const* d_in, const int* in_sizes, int n_in,
                              void* d_out, int out_size) {
    const float* x   = (const float*)d_in[0];
    const float* w1  = (const float*)d_in[1];
    const float* b1  = (const float*)d_in[2];
    const float* g1  = (const float*)d_in[3];
    const float* be1 = (const float*)d_in[4];
    const float* m1  = (const float*)d_in[5];
    const float* v1  = (const float*)d_in[6];
    const float* wg  = (const float*)d_in[7];
    const float* bg  = (const float*)d_in[8];
    const float* gg  = (const float*)d_in[9];
    const float* beg = (const float*)d_in[10];
    const float* mg  = (const float*)d_in[11];
    const float* vg  = (const float*)d_in[12];
    const float* w2  = (const float*)d_in[13];
    const float* b2  = (const float*)d_in[14];
    const float* g2  = (const float*)d_in[15];
    const float* be2 = (const float*)d_in[16];
    const float* m2  = (const float*)d_in[17];
    const float* v2  = (const float*)d_in[18];

    __nv_bfloat16 *xTp, *catp, *gp, *w1p, *wgp, *w2p;
    float *tmp2, *sc1, *sh1, *scg, *shg, *sc2, *sh2;
    cudaGetSymbolAddress((void**)&xTp, g_xTp);
    cudaGetSymbolAddress((void**)&catp, g_catp);
    cudaGetSymbolAddress((void**)&gp, g_gp);
    cudaGetSymbolAddress((void**)&w1p, g_w1p);
    cudaGetSymbolAddress((void**)&wgp, g_wgp);
    cudaGetSymbolAddress((void**)&w2p, g_w2p);
    cudaGetSymbolAddress((void**)&tmp2, g_tmp2);
    cudaGetSymbolAddress((void**)&sc1, g_sc1);
    cudaGetSymbolAddress((void**)&sh1, g_sh1);
    cudaGetSymbolAddress((void**)&scg, g_scg);
    cudaGetSymbolAddress((void**)&shg, g_shg);
    cudaGetSymbolAddress((void**)&sc2, g_sc2);
    cudaGetSymbolAddress((void**)&sh2, g_sh2);

    cudaFuncSetAttribute(bf16_gemm<0>, cudaFuncAttributeMaxDynamicSharedMemorySize, GSMEM);
    cudaFuncSetAttribute(bf16_gemm<1>, cudaFuncAttributeMaxDynamicSharedMemorySize, GSMEM);
    cudaFuncSetAttribute(bf16_gemm<2>, cudaFuncAttributeMaxDynamicSharedMemorySize, GSMEM);

    prep_kernel<<<1, 512>>>(b1, g1, be1, m1, v1, bg, gg, beg, mg, vg,
                            b2, g2, be2, m2, v2);
    pack_w<<<(DIM * DIM) / 256, 256>>>(w1, w1p, DIM);
    pack_w<<<(DIM2 * DIM2) / 256, 256>>>(wg, wgp, DIM2);
    pack_w<<<(DIM * DIM2) / 256, 256>>>(w2, w2p, DIM2);
    transpose_in_pack<<<dim3(98, 8, 8), 256>>>(x);

    // fc1: cat[:,0:256] (packed) = BN(x @ w1^T)
    bf16_gemm<0><<<dim3(196, 2), 256, GSMEM>>>(xTp, w1p, catp, sc1, sh1, 3 * DIM);
    // MRConv4d -> cat[:,256:512] (packed)
    colmin_kernel<<<dim3(56, 8), 256>>>();
    row_combine_kernel<<<dim3(56, 8), 256>>>();
    // gbuf (packed) = GELU(BN(cat @ wg^T))
    bf16_gemm<1><<<dim3(196, 4), 256, GSMEM>>>(catp, wgp, gp, scg, shg, 3 * DIM2);
    // tmp2 = BN(g @ w2^T)
    bf16_gemm<2><<<dim3(196, 2), 256, GSMEM>>>(gp, w2p, tmp2, sc2, sh2, 3 * DIM2);
    // out = tmp2^T + x
    transpose_out_res<<<dim3(98, 8, 8), 256>>>(x, (float*)d_out);
}

// round 4
// speedup vs baseline: 2.7874x; 1.4264x over previous
#include <cuda_runtime.h>
#include <cuda_fp16.h>
#include <cstdint>

#define SPX 3136      // 56*56
#define BATCH 8
#define DIM 256
#define DIM2 512
#define ROWS_TOT (BATCH * SPX)   // 25088 = 196 * 128

// ---------------- scratch (static __device__, allocation-free) ----------------
__device__ __half g_xTp[(size_t)ROWS_TOT * 2 * DIM];    // [B*S, 512] = [hi(x) | lo(x)]
__device__ __half g_catp[(size_t)ROWS_TOT * 2 * DIM2];  // [B*S, 1024] = [hi(cat 512) | lo(cat 512)]
__device__ __half g_gp[(size_t)ROWS_TOT * 2 * DIM2];    // [B*S, 1024] = [hi(g) | lo(g)]
__device__ __half g_w1h[(size_t)DIM * DIM];             // fp16(w1) [256,256]
__device__ __half g_wgh[(size_t)DIM2 * DIM2];           // fp16(wg) [512,512]
__device__ __half g_w2h[(size_t)DIM * DIM2];            // fp16(w2) [256,512]
__device__ float g_cm1[(size_t)BATCH * 56 * 2 * DIM], g_cm2[(size_t)BATCH * 56 * 2 * DIM];
__device__ float g_sc1[DIM], g_sh1[DIM];
__device__ float g_scg[DIM2], g_shg[DIM2];
__device__ float g_sc2[DIM], g_sh2[DIM];

// ---------------- PTX helpers (sm_80-generic only) ----------------
__device__ __forceinline__ uint32_t smem_u32(const void* p) {
    uint32_t a;
    asm("{ .reg .u64 t; cvta.to.shared.u64 t, %1; cvt.u32.u64 %0, t; }" : "=r"(a) : "l"(p));
    return a;
}
#define CP_ASYNC16(sm, gm) \
    asm volatile("cp.async.cg.shared.global [%0], [%1], 16;" :: "r"(sm), "l"(gm) : "memory")
#define CP_COMMIT() asm volatile("cp.async.commit_group;" ::: "memory")
#define CP_WAIT1() asm volatile("cp.async.wait_group 1;" ::: "memory")
#define CP_WAIT0() asm volatile("cp.async.wait_group 0;" ::: "memory")
#define LDSM_X4(r0, r1, r2, r3, addr)                                        \
    asm volatile("ldmatrix.sync.aligned.m8n8.x4.shared.b16 {%0,%1,%2,%3}, [%4];" \
                 : "=r"(r0), "=r"(r1), "=r"(r2), "=r"(r3) : "r"(addr))

__device__ __forceinline__ void mma_fp16(float* d, const uint32_t* a, const uint32_t* b) {
    asm volatile(
        "mma.sync.aligned.m16n8k16.row.col.f32.f16.f16.f32 "
        "{%0,%1,%2,%3}, {%4,%5,%6,%7}, {%8,%9}, {%0,%1,%2,%3};"
        : "+f"(d[0]), "+f"(d[1]), "+f"(d[2]), "+f"(d[3])
        : "r"(a[0]), "r"(a[1]), "r"(a[2]), "r"(a[3]), "r"(b[0]), "r"(b[1]));
}

__device__ __forceinline__ void split2(float v, __half& hi, __half& lo) {
    hi = __float2half_rn(v);
    lo = __float2half_rn(v - __half2float(hi));
}

// ---------------- prep: fold conv bias + BN ----------------
__global__ void prep_kernel(const float* __restrict__ b1, const float* __restrict__ g1,
                            const float* __restrict__ be1, const float* __restrict__ m1,
                            const float* __restrict__ v1,
                            const float* __restrict__ bg, const float* __restrict__ gg,
                            const float* __restrict__ beg, const float* __restrict__ mg,
                            const float* __restrict__ vg,
                            const float* __restrict__ b2, const float* __restrict__ g2,
                            const float* __restrict__ be2, const float* __restrict__ m2,
                            const float* __restrict__ v2) {
    int i = threadIdx.x;  // 512
    if (i < DIM) {
        float s = g1[i] / sqrtf(v1[i] + 1e-5f);
        g_sc1[i] = s; g_sh1[i] = (b1[i] - m1[i]) * s + be1[i];
        float s2 = g2[i] / sqrtf(v2[i] + 1e-5f);
        g_sc2[i] = s2; g_sh2[i] = (b2[i] - m2[i]) * s2 + be2[i];
    }
    float sg = gg[i] / sqrtf(vg[i] + 1e-5f);
    g_scg[i] = sg; g_shg[i] = (bg[i] - mg[i]) * sg + beg[i];
}

// ---------------- weight convert: fp16(W), same [N,K] layout ----------------
__global__ void pack_w(const float* __restrict__ W, __half* __restrict__ Wp) {
    int idx = blockIdx.x * 256 + threadIdx.x;
    Wp[idx] = __float2half_rn(W[idx]);
}

// ---------------- transpose x [B,256,S] -> [B*S, 512] = [hi | lo] ----------------
__global__ void __launch_bounds__(256) transpose_in_pack(const float* __restrict__ x) {
    __shared__ float t[32][33];
    int tx = threadIdx.x & 31, ty = threadIdx.x >> 5;
    int s0 = blockIdx.x * 32, c0 = blockIdx.y * 32, b = blockIdx.z;
    const float* xp = x + ((size_t)b * DIM + c0) * SPX + s0;
    for (int i = ty; i < 32; i += 8) t[i][tx] = xp[(size_t)i * SPX + tx];
    __syncthreads();
    __half* op = g_xTp + ((size_t)(b * SPX + s0)) * (2 * DIM) + c0;
    for (int i = ty; i < 32; i += 8) {
        float v = t[tx][i];
        __half hi, lo;
        split2(v, hi, lo);
        __half* r = op + (size_t)i * (2 * DIM);
        r[tx] = hi; r[DIM + tx] = lo;
    }
}

// ---------------- MRConv4d on packed cat [B*S, 1024] ----------------
// h[r,c] = catp[r, c] + catp[r, 512+c], c in [0,256)
// xj -> hi at col 256+c, lo at col 768+c
__global__ void __launch_bounds__(256) colmin_kernel() {
    int x = blockIdx.x, b = blockIdx.y, c = threadIdx.x;
    const __half* base = g_catp + ((size_t)b * SPX) * 1024 + c;
    float a1e = 1e30f, a2e = 1e30f, a1o = 1e30f, a2o = 1e30f;
    for (int y = 0; y < 56; y += 2) {
        size_t p0 = (size_t)(y * 56 + x) * 1024;
        float v = __half2float(base[p0]) + __half2float(base[p0 + 512]);
        if (v < a1e) { a2e = a1e; a1e = v; } else if (v < a2e) a2e = v;
        size_t p1 = (size_t)((y + 1) * 56 + x) * 1024;
        float w = __half2float(base[p1]) + __half2float(base[p1 + 512]);
        if (w < a1o) { a2o = a1o; a1o = w; } else if (w < a2o) a2o = w;
    }
    size_t o = ((size_t)(b * 56 + x) * 2) * DIM + c;
    g_cm1[o] = a1e; g_cm2[o] = a2e;
    g_cm1[o + DIM] = a1o; g_cm2[o + DIM] = a2o;
}

__global__ void __launch_bounds__(256) row_combine_kernel() {
    int y = blockIdx.x, b = blockIdx.y, c = threadIdx.x;
    const __half* base = g_catp + ((size_t)(b * SPX + y * 56)) * 1024 + c;
    float r1e = 1e30f, r2e = 1e30f, r1o = 1e30f, r2o = 1e30f;
    float hv[56];
    for (int x = 0; x < 56; x += 2) {
        size_t p0 = (size_t)x * 1024;
        float v = __half2float(base[p0]) + __half2float(base[p0 + 512]);
        hv[x] = v;
        if (v < r1e) { r2e = r1e; r1e = v; } else if (v < r2e) r2e = v;
        size_t p1 = (size_t)(x + 1) * 1024;
        float w = __half2float(base[p1]) + __half2float(base[p1 + 512]);
        hv[x + 1] = w;
        if (w < r1o) { r2o = r1o; r1o = w; } else if (w < r2o) r2o = w;
    }
    int py = y & 1;
    __half* ob = g_catp + ((size_t)(b * SPX + y * 56)) * 1024 + c;
    for (int x = 0; x < 56; x++) {
        float v = hv[x];
        size_t o = ((size_t)(b * 56 + x) * 2 + py) * DIM + c;
        float c1 = g_cm1[o], c2 = g_cm2[o];
        float ec = (v == c1) ? c2 : c1;
        float m1r = (x & 1) ? r1o : r1e, m2r = (x & 1) ? r2o : r2e;
        float er = (v == m1r) ? m2r : m1r;
        float xj = fmaxf(0.0f, v - fminf(ec, er));
        __half hi, lo;
        split2(xj, hi, lo);
        __half* r = ob + (size_t)x * 1024;
        r[256] = hi;   // hi(xj)
        r[768] = lo;   // lo(xj) = 512 + 256 + c
    }
}

// ---------------- fp16 mma.sync GEMM (2-term exact-activation split) ----------------
// D[r,n] = sum_{k'<Kp} A''[r0+r,k'] * Wh[n0+n, k' % Kw]
// A'' = [hi(A) | lo(A)] (exact), Wh = fp16(W) -> D = sum A * fp16(W)
// Tile 128x128, BK=64, cp.async double buffer, 8 warps (2m x 4n), 64x32/warp.
// MODE 0: BN -> packed [hi|lo] row-stride 1024 (fc1)
// MODE 1: BN + GELU -> packed [hi|lo] row-stride 1024 (gemm2)
// MODE 2: BN + residual -> TRANSPOSED fp32 write to out[B,256,S] via smem staging
#define GSMEM 66560
template <int MODE>
__global__ void __launch_bounds__(256, 2)
fp16_gemm(const __half* __restrict__ Ag, const __half* __restrict__ Wg,
          void* __restrict__ dstv, const float* __restrict__ xres,
          const float* __restrict__ scale, const float* __restrict__ shift,
          int Kp, int Kw) {
    extern __shared__ __align__(1024) char smem[];
    __shared__ float s_scale[128], s_shift[128];
    const int tid = threadIdx.x, lane = tid & 31, wid = tid >> 5;
    const int warp_m = wid >> 2, warp_n = wid & 3;
    const int r0 = blockIdx.x * 128, n0 = blockIdx.y * 128;
    const uint32_t sb = smem_u32(smem);
    if (tid < 128) { s_scale[tid] = scale[n0 + tid]; s_shift[tid] = shift[n0 + tid]; }

    uint32_t loff[4];
    size_t aoff[4], boff[4];
#pragma unroll
    for (int i = 0; i < 4; i++) {
        int idx = tid + i * 256;
        int row = idx >> 3, c = idx & 7;
        loff[i] = row * 128 + ((c ^ (row & 7)) << 4);
        aoff[i] = (size_t)(r0 + row) * Kp + c * 8;
        boff[i] = (size_t)(n0 + row) * Kw + c * 8;
    }

    const int rowA[4] = {warp_m * 64 + 0 * 16 + (lane & 7) + ((lane >> 3) & 1) * 8,
                         warp_m * 64 + 1 * 16 + (lane & 7) + ((lane >> 3) & 1) * 8,
                         warp_m * 64 + 2 * 16 + (lane & 7) + ((lane >> 3) & 1) * 8,
                         warp_m * 64 + 3 * 16 + (lane & 7) + ((lane >> 3) & 1) * 8};
    const int kcA = lane >> 4;
    const int rowB[2] = {warp_n * 32 + 0 * 16 + (lane & 7) + ((lane >> 4) & 1) * 8,
                         warp_n * 32 + 1 * 16 + (lane & 7) + ((lane >> 4) & 1) * 8};
    const int kcB = (lane >> 3) & 1;

    float acc[4][4][4];
#pragma unroll
    for (int a = 0; a < 4; a++)
#pragma unroll
        for (int b = 0; b < 4; b++)
#pragma unroll
            for (int i = 0; i < 4; i++) acc[a][b][i] = 0.0f;

    const int NS = Kp >> 6;

    // prologue: stage 0 -> buf 0 (W offset 0)
#pragma unroll
    for (int i = 0; i < 4; i++) {
        CP_ASYNC16(sb + loff[i], Ag + aoff[i]);
        CP_ASYNC16(sb + 16384 + loff[i], Wg + boff[i]);
    }
    CP_COMMIT();

    for (int s = 0; s < NS; s++) {
        const int buf = s & 1;
        if (s + 1 < NS) {
            const uint32_t nb = sb + (buf ^ 1) * 32768;
            const size_t kA = (size_t)(s + 1) * 64;
            const int kW = ((s + 1) * 64) % Kw;
#pragma unroll
            for (int i = 0; i < 4; i++) {
                CP_ASYNC16(nb + loff[i], Ag + aoff[i] + kA);
                CP_ASYNC16(nb + 16384 + loff[i], Wg + boff[i] + kW);
            }
            CP_COMMIT();
            CP_WAIT1();
        } else {
            CP_WAIT0();
        }
        __syncthreads();

        const uint32_t aBase = sb + buf * 32768;
        const uint32_t bBase = aBase + 16384;
#pragma unroll
        for (int kk = 0; kk < 4; kk++) {
            uint32_t af[4][4];
#pragma unroll
            for (int mf = 0; mf < 4; mf++) {
                uint32_t addr = aBase + rowA[mf] * 128 +
                                (((kk * 2 + kcA) ^ (rowA[mf] & 7)) << 4);
                LDSM_X4(af[mf][0], af[mf][1], af[mf][2], af[mf][3], addr);
            }
            uint32_t bf[2][4];
#pragma unroll
            for (int nb2 = 0; nb2 < 2; nb2++) {
                uint32_t addr = bBase + rowB[nb2] * 128 +
                                (((kk * 2 + kcB) ^ (rowB[nb2] & 7)) << 4);
                LDSM_X4(bf[nb2][0], bf[nb2][1], bf[nb2][2], bf[nb2][3], addr);
            }
#pragma unroll
            for (int mf = 0; mf < 4; mf++)
#pragma unroll
                for (int nf = 0; nf < 4; nf++)
                    mma_fp16(acc[mf][nf], af[mf], &bf[nf >> 1][(nf & 1) * 2]);
        }
        __syncthreads();
    }

    // ---------------- epilogue ----------------
    if (MODE == 2) {
        // BN + staged transpose + residual write to out[B, 256, S]
        float* stg = (float*)smem;  // pitch 129 floats, 128x129*4 = 66048 B
#pragma unroll
        for (int mf = 0; mf < 4; mf++)
#pragma unroll
            for (int nf = 0; nf < 4; nf++)
#pragma unroll
                for (int half = 0; half < 2; half++) {
                    int rl = warp_m * 64 + mf * 16 + (lane >> 2) + half * 8;
                    int cl = warp_n * 32 + nf * 8 + (lane & 3) * 2;
                    float v0 = fmaf(acc[mf][nf][half * 2 + 0], s_scale[cl], s_shift[cl]);
                    float v1 = fmaf(acc[mf][nf][half * 2 + 1], s_scale[cl + 1], s_shift[cl + 1]);
                    stg[rl * 129 + cl] = v0;
                    stg[rl * 129 + cl + 1] = v1;
                }
        __syncthreads();
        float* out = (float*)dstv;
#pragma unroll
        for (int cc = 0; cc < 16; cc++) {
            int c = wid * 16 + cc;
#pragma unroll
            for (int j = 0; j < 4; j++) {
                int i = lane + 32 * j;
                int r = r0 + i;
                int b = r / SPX;
                size_t o = ((size_t)(b * DIM + n0 + c)) * SPX + (r - b * SPX);
                out[o] = stg[i * 129 + c] + xres[o];
            }
        }
        return;
    }

    const int mw = r0 + warp_m * 64;
    const int nw = warp_n * 32;
    __half* dp_base = (__half*)dstv;
#pragma unroll
    for (int mf = 0; mf < 4; mf++) {
#pragma unroll
        for (int nf = 0; nf < 4; nf++) {
#pragma unroll
            for (int half = 0; half < 2; half++) {
                int grow = mw + mf * 16 + (lane >> 2) + half * 8;
                int lcol = nw + nf * 8 + (lane & 3) * 2;
                float v0 = fmaf(acc[mf][nf][half * 2 + 0], s_scale[lcol], s_shift[lcol]);
                float v1 = fmaf(acc[mf][nf][half * 2 + 1], s_scale[lcol + 1], s_shift[lcol + 1]);
                if (MODE == 1) {
                    v0 = 0.5f * v0 * (1.0f + erff(v0 * 0.70710678118654752f));
                    v1 = 0.5f * v1 * (1.0f + erff(v1 * 0.70710678118654752f));
                }
                __half h0, l0, h1, l1;
                split2(v0, h0, l0);
                split2(v1, h1, l1);
                __half2 hp; hp.x = h0; hp.y = h1;
                __half2 lp; lp.x = l0; lp.y = l1;
                __half* dp = dp_base + (size_t)grow * 1024 + n0 + lcol;
                *(__half2*)(dp) = hp;
                *(__half2*)(dp + 512) = lp;
            }
        }
    }
}

// ---------------------------------------------------------------------------
extern "C" void kernel_launch(void* const* d_in, const int* in_sizes, int n_in,
                              void* d_out, int out_size) {
    const float* x   = (const float*)d_in[0];
    const float* w1  = (const float*)d_in[1];
    const float* b1  = (const float*)d_in[2];
    const float* g1  = (const float*)d_in[3];
    const float* be1 = (const float*)d_in[4];
    const float* m1  = (const float*)d_in[5];
    const float* v1  = (const float*)d_in[6];
    const float* wg  = (const float*)d_in[7];
    const float* bg  = (const float*)d_in[8];
    const float* gg  = (const float*)d_in[9];
    const float* beg = (const float*)d_in[10];
    const float* mg  = (const float*)d_in[11];
    const float* vg  = (const float*)d_in[12];
    const float* w2  = (const float*)d_in[13];
    const float* b2  = (const float*)d_in[14];
    const float* g2  = (const float*)d_in[15];
    const float* be2 = (const float*)d_in[16];
    const float* m2  = (const float*)d_in[17];
    const float* v2  = (const float*)d_in[18];

    __half *xTp, *catp, *gp, *w1h, *wgh, *w2h;
    float *sc1, *sh1, *scg, *shg, *sc2, *sh2;
    cudaGetSymbolAddress((void**)&xTp, g_xTp);
    cudaGetSymbolAddress((void**)&catp, g_catp);
    cudaGetSymbolAddress((void**)&gp, g_gp);
    cudaGetSymbolAddress((void**)&w1h, g_w1h);
    cudaGetSymbolAddress((void**)&wgh, g_wgh);
    cudaGetSymbolAddress((void**)&w2h, g_w2h);
    cudaGetSymbolAddress((void**)&sc1, g_sc1);
    cudaGetSymbolAddress((void**)&sh1, g_sh1);
    cudaGetSymbolAddress((void**)&scg, g_scg);
    cudaGetSymbolAddress((void**)&shg, g_shg);
    cudaGetSymbolAddress((void**)&sc2, g_sc2);
    cudaGetSymbolAddress((void**)&sh2, g_sh2);

    cudaFuncSetAttribute(fp16_gemm<0>, cudaFuncAttributeMaxDynamicSharedMemorySize, GSMEM);
    cudaFuncSetAttribute(fp16_gemm<1>, cudaFuncAttributeMaxDynamicSharedMemorySize, GSMEM);
    cudaFuncSetAttribute(fp16_gemm<2>, cudaFuncAttributeMaxDynamicSharedMemorySize, GSMEM);

    prep_kernel<<<1, 512>>>(b1, g1, be1, m1, v1, bg, gg, beg, mg, vg,
                            b2, g2, be2, m2, v2);
    pack_w<<<(DIM * DIM) / 256, 256>>>(w1, w1h);
    pack_w<<<(DIM2 * DIM2) / 256, 256>>>(wg, wgh);
    pack_w<<<(DIM * DIM2) / 256, 256>>>(w2, w2h);
    transpose_in_pack<<<dim3(98, 8, 8), 256>>>(x);

    // fc1: cat[:, 0:256] (hi/lo packed) = BN(x @ w1^T)
    fp16_gemm<0><<<dim3(196, 2), 256, GSMEM>>>(xTp, w1h, catp, nullptr, sc1, sh1,
                                               2 * DIM, DIM);
    // MRConv4d -> cat[:, 256:512] (hi/lo packed)
    colmin_kernel<<<dim3(56, 8), 256>>>();
    row_combine_kernel<<<dim3(56, 8), 256>>>();
    // g (hi/lo packed) = GELU(BN(cat @ wg^T))
    fp16_gemm<1><<<dim3(196, 4), 256, GSMEM>>>(catp, wgh, gp, nullptr, scg, shg,
                                               2 * DIM2, DIM2);
    // out[B,256,S] = BN(g @ w2^T)^T + x  (fused transpose + residual)
    fp16_gemm<2><<<dim3(196, 2), 256, GSMEM>>>(gp, w2h, d_out, x, sc2, sh2,
                                               2 * DIM2, DIM2);
}

// round 5
// speedup vs baseline: 4.5085x; 1.6175x over previous
#include <cuda_runtime.h>
#include <cuda_fp16.h>
#include <cstdint>

#define SPX 3136      // 56*56
#define BATCH 8
#define DIM 256
#define DIM2 512
#define ROWS_TOT (BATCH * SPX)   // 25088 = 196 * 128

// ---------------- scratch (static __device__, allocation-free) ----------------
__device__ __half g_xTh[(size_t)ROWS_TOT * DIM];     // fp16(x^T) [B*S, 256]
__device__ __half g_cath[(size_t)ROWS_TOT * DIM2];   // [B*S, 512] = [h | xj]
__device__ __half g_gh[(size_t)ROWS_TOT * DIM2];     // gelu out [B*S, 512]
__device__ __half g_w1h[(size_t)DIM * DIM];          // fp16(w1) [256,256]
__device__ __half g_wgh[(size_t)DIM2 * DIM2];        // fp16(wg) [512,512]
__device__ __half g_w2h[(size_t)DIM * DIM2];         // fp16(w2) [256,512]
__device__ float g_cm1[(size_t)BATCH * 56 * 2 * DIM], g_cm2[(size_t)BATCH * 56 * 2 * DIM];
__device__ float g_sc1[DIM], g_sh1[DIM];
__device__ float g_scg[DIM2], g_shg[DIM2];
__device__ float g_sc2[DIM], g_sh2[DIM];

// ---------------- PTX helpers (sm_80-generic only) ----------------
__device__ __forceinline__ uint32_t smem_u32(const void* p) {
    uint32_t a;
    asm("{ .reg .u64 t; cvta.to.shared.u64 t, %1; cvt.u32.u64 %0, t; }" : "=r"(a) : "l"(p));
    return a;
}
#define CP_ASYNC16(sm, gm) \
    asm volatile("cp.async.cg.shared.global [%0], [%1], 16;" :: "r"(sm), "l"(gm) : "memory")
#define CP_COMMIT() asm volatile("cp.async.commit_group;" ::: "memory")
#define CP_WAIT1() asm volatile("cp.async.wait_group 1;" ::: "memory")
#define CP_WAIT0() asm volatile("cp.async.wait_group 0;" ::: "memory")
#define LDSM_X4(r0, r1, r2, r3, addr)                                        \
    asm volatile("ldmatrix.sync.aligned.m8n8.x4.shared.b16 {%0,%1,%2,%3}, [%4];" \
                 : "=r"(r0), "=r"(r1), "=r"(r2), "=r"(r3) : "r"(addr))

__device__ __forceinline__ void mma_fp16(float* d, const uint32_t* a, const uint32_t* b) {
    asm volatile(
        "mma.sync.aligned.m16n8k16.row.col.f32.f16.f16.f32 "
        "{%0,%1,%2,%3}, {%4,%5,%6,%7}, {%8,%9}, {%0,%1,%2,%3};"
        : "+f"(d[0]), "+f"(d[1]), "+f"(d[2]), "+f"(d[3])
        : "r"(a[0]), "r"(a[1]), "r"(a[2]), "r"(a[3]), "r"(b[0]), "r"(b[1]));
}

// ---------------- fused prep + weight packing ----------------
// blocks [0, 1792): convert w1|wg|w2 to fp16 (flat index over 458752 elems)
// block 1792: fold conv bias + BN into scale/shift
__global__ void prep_pack(const float* __restrict__ w1, const float* __restrict__ wg,
                          const float* __restrict__ w2,
                          const float* __restrict__ b1, const float* __restrict__ g1,
                          const float* __restrict__ be1, const float* __restrict__ m1,
                          const float* __restrict__ v1,
                          const float* __restrict__ bg, const float* __restrict__ gg,
                          const float* __restrict__ beg, const float* __restrict__ mg,
                          const float* __restrict__ vg,
                          const float* __restrict__ b2, const float* __restrict__ g2,
                          const float* __restrict__ be2, const float* __restrict__ m2,
                          const float* __restrict__ v2) {
    int blk = blockIdx.x;
    if (blk < 1792) {
        int idx = blk * 256 + threadIdx.x;
        if (idx < 65536) {
            g_w1h[idx] = __float2half_rn(w1[idx]);
        } else if (idx < 65536 + 262144) {
            int j = idx - 65536;
            g_wgh[j] = __float2half_rn(wg[j]);
        } else {
            int j = idx - 65536 - 262144;
            g_w2h[j] = __float2half_rn(w2[j]);
        }
        return;
    }
    // prep (256 threads, channels i and i+256)
    int i = threadIdx.x;
    {
        float s = g1[i] / sqrtf(v1[i] + 1e-5f);
        g_sc1[i] = s; g_sh1[i] = (b1[i] - m1[i]) * s + be1[i];
        float s2 = g2[i] / sqrtf(v2[i] + 1e-5f);
        g_sc2[i] = s2; g_sh2[i] = (b2[i] - m2[i]) * s2 + be2[i];
    }
#pragma unroll
    for (int r = 0; r < 2; r++) {
        int j = i + r * 256;
        float sg = gg[j] / sqrtf(vg[j] + 1e-5f);
        g_scg[j] = sg; g_shg[j] = (bg[j] - mg[j]) * sg + beg[j];
    }
}

// ---------------- transpose x [B,256,S] -> fp16 [B*S, 256] ----------------
__global__ void __launch_bounds__(256) transpose_in_pack(const float* __restrict__ x) {
    __shared__ float t[32][33];
    int tx = threadIdx.x & 31, ty = threadIdx.x >> 5;
    int s0 = blockIdx.x * 32, c0 = blockIdx.y * 32, b = blockIdx.z;
    const float* xp = x + ((size_t)b * DIM + c0) * SPX + s0;
    for (int i = ty; i < 32; i += 8) t[i][tx] = xp[(size_t)i * SPX + tx];
    __syncthreads();
    __half* op = g_xTh + ((size_t)(b * SPX + s0)) * DIM + c0;
    for (int i = ty; i < 32; i += 8)
        op[(size_t)i * DIM + tx] = __float2half_rn(t[tx][i]);
}

// ---------------- MRConv4d on cat [B*S, 512]: h at col c, xj at col 256+c ----------------
__global__ void __launch_bounds__(256) colmin_kernel() {
    int x = blockIdx.x, b = blockIdx.y, c = threadIdx.x;
    const __half* base = g_cath + ((size_t)b * SPX) * DIM2 + c;
    float a1e = 1e30f, a2e = 1e30f, a1o = 1e30f, a2o = 1e30f;
    for (int y = 0; y < 56; y += 2) {
        float v = __half2float(base[(size_t)(y * 56 + x) * DIM2]);
        if (v < a1e) { a2e = a1e; a1e = v; } else if (v < a2e) a2e = v;
        float w = __half2float(base[(size_t)((y + 1) * 56 + x) * DIM2]);
        if (w < a1o) { a2o = a1o; a1o = w; } else if (w < a2o) a2o = w;
    }
    size_t o = ((size_t)(b * 56 + x) * 2) * DIM + c;
    g_cm1[o] = a1e; g_cm2[o] = a2e;
    g_cm1[o + DIM] = a1o; g_cm2[o + DIM] = a2o;
}

__global__ void __launch_bounds__(256) row_combine_kernel() {
    int y = blockIdx.x, b = blockIdx.y, c = threadIdx.x;
    const __half* base = g_cath + ((size_t)(b * SPX + y * 56)) * DIM2 + c;
    float r1e = 1e30f, r2e = 1e30f, r1o = 1e30f, r2o = 1e30f;
    float hv[56];
    for (int x = 0; x < 56; x += 2) {
        float v = __half2float(base[(size_t)x * DIM2]);
        hv[x] = v;
        if (v < r1e) { r2e = r1e; r1e = v; } else if (v < r2e) r2e = v;
        float w = __half2float(base[(size_t)(x + 1) * DIM2]);
        hv[x + 1] = w;
        if (w < r1o) { r2o = r1o; r1o = w; } else if (w < r2o) r2o = w;
    }
    int py = y & 1;
    __half* ob = g_cath + ((size_t)(b * SPX + y * 56)) * DIM2 + DIM + c;
    for (int x = 0; x < 56; x++) {
        float v = hv[x];
        size_t o = ((size_t)(b * 56 + x) * 2 + py) * DIM + c;
        float c1 = g_cm1[o], c2 = g_cm2[o];
        float ec = (v == c1) ? c2 : c1;
        float m1r = (x & 1) ? r1o : r1e, m2r = (x & 1) ? r2o : r2e;
        float er = (v == m1r) ? m2r : m1r;
        ob[(size_t)x * DIM2] = __float2half_rn(fmaxf(0.0f, v - fminf(ec, er)));
    }
}

// ---------------- fp16 mma.sync GEMM ----------------
// D[r,n] = sum_k A[r0+r,k] * W[n0+n,k]
// Tile 128x128, BK=64, cp.async double buffer, 8 warps (2m x 4n), 64x32/warp.
// MODE 0: BN -> fp16 write, row stride 512 (fc1: h)
// MODE 1: BN + exact GELU -> fp16 write, row stride 512 (gemm2)
// MODE 2: BN + residual -> TRANSPOSED fp32 write to out[B,256,S] via smem staging
#define GSMEM 66560
template <int MODE>
__global__ void __launch_bounds__(256, 2)
fp16_gemm(const __half* __restrict__ Ag, const __half* __restrict__ Wg,
          void* __restrict__ dstv, const float* __restrict__ xres,
          const float* __restrict__ scale, const float* __restrict__ shift, int K) {
    extern __shared__ __align__(1024) char smem[];
    __shared__ float s_scale[128], s_shift[128];
    const int tid = threadIdx.x, lane = tid & 31, wid = tid >> 5;
    const int warp_m = wid >> 2, warp_n = wid & 3;
    const int r0 = blockIdx.x * 128, n0 = blockIdx.y * 128;
    const uint32_t sb = smem_u32(smem);
    if (tid < 128) { s_scale[tid] = scale[n0 + tid]; s_shift[tid] = shift[n0 + tid]; }

    uint32_t loff[4];
    size_t aoff[4], boff[4];
#pragma unroll
    for (int i = 0; i < 4; i++) {
        int idx = tid + i * 256;
        int row = idx >> 3, c = idx & 7;
        loff[i] = row * 128 + ((c ^ (row & 7)) << 4);
        aoff[i] = (size_t)(r0 + row) * K + c * 8;
        boff[i] = (size_t)(n0 + row) * K + c * 8;
    }

    const int rowA[4] = {warp_m * 64 + 0 * 16 + (lane & 7) + ((lane >> 3) & 1) * 8,
                         warp_m * 64 + 1 * 16 + (lane & 7) + ((lane >> 3) & 1) * 8,
                         warp_m * 64 + 2 * 16 + (lane & 7) + ((lane >> 3) & 1) * 8,
                         warp_m * 64 + 3 * 16 + (lane & 7) + ((lane >> 3) & 1) * 8};
    const int kcA = lane >> 4;
    const int rowB[2] = {warp_n * 32 + 0 * 16 + (lane & 7) + ((lane >> 4) & 1) * 8,
                         warp_n * 32 + 1 * 16 + (lane & 7) + ((lane >> 4) & 1) * 8};
    const int kcB = (lane >> 3) & 1;

    float acc[4][4][4];
#pragma unroll
    for (int a = 0; a < 4; a++)
#pragma unroll
        for (int b = 0; b < 4; b++)
#pragma unroll
            for (int i = 0; i < 4; i++) acc[a][b][i] = 0.0f;

    const int NS = K >> 6;

    // prologue: stage 0 -> buf 0
#pragma unroll
    for (int i = 0; i < 4; i++) {
        CP_ASYNC16(sb + loff[i], Ag + aoff[i]);
        CP_ASYNC16(sb + 16384 + loff[i], Wg + boff[i]);
    }
    CP_COMMIT();

    for (int s = 0; s < NS; s++) {
        const int buf = s & 1;
        if (s + 1 < NS) {
            const uint32_t nb = sb + (buf ^ 1) * 32768;
            const size_t kadd = (size_t)(s + 1) * 64;
#pragma unroll
            for (int i = 0; i < 4; i++) {
                CP_ASYNC16(nb + loff[i], Ag + aoff[i] + kadd);
                CP_ASYNC16(nb + 16384 + loff[i], Wg + boff[i] + kadd);
            }
            CP_COMMIT();
            CP_WAIT1();
        } else {
            CP_WAIT0();
        }
        __syncthreads();

        const uint32_t aBase = sb + buf * 32768;
        const uint32_t bBase = aBase + 16384;
#pragma unroll
        for (int kk = 0; kk < 4; kk++) {
            uint32_t af[4][4];
#pragma unroll
            for (int mf = 0; mf < 4; mf++) {
                uint32_t addr = aBase + rowA[mf] * 128 +
                                (((kk * 2 + kcA) ^ (rowA[mf] & 7)) << 4);
                LDSM_X4(af[mf][0], af[mf][1], af[mf][2], af[mf][3], addr);
            }
            uint32_t bf[2][4];
#pragma unroll
            for (int nb2 = 0; nb2 < 2; nb2++) {
                uint32_t addr = bBase + rowB[nb2] * 128 +
                                (((kk * 2 + kcB) ^ (rowB[nb2] & 7)) << 4);
                LDSM_X4(bf[nb2][0], bf[nb2][1], bf[nb2][2], bf[nb2][3], addr);
            }
#pragma unroll
            for (int mf = 0; mf < 4; mf++)
#pragma unroll
                for (int nf = 0; nf < 4; nf++)
                    mma_fp16(acc[mf][nf], af[mf], &bf[nf >> 1][(nf & 1) * 2]);
        }
        __syncthreads();
    }

    // ---------------- epilogue ----------------
    if (MODE == 2) {
        float* stg = (float*)smem;  // pitch 129 floats
#pragma unroll
        for (int mf = 0; mf < 4; mf++)
#pragma unroll
            for (int nf = 0; nf < 4; nf++)
#pragma unroll
                for (int half = 0; half < 2; half++) {
                    int rl = warp_m * 64 + mf * 16 + (lane >> 2) + half * 8;
                    int cl = warp_n * 32 + nf * 8 + (lane & 3) * 2;
                    stg[rl * 129 + cl] = fmaf(acc[mf][nf][half * 2 + 0], s_scale[cl], s_shift[cl]);
                    stg[rl * 129 + cl + 1] =
                        fmaf(acc[mf][nf][half * 2 + 1], s_scale[cl + 1], s_shift[cl + 1]);
                }
        __syncthreads();
        float* out = (float*)dstv;
#pragma unroll
        for (int cc = 0; cc < 16; cc++) {
            int c = wid * 16 + cc;
#pragma unroll
            for (int j = 0; j < 4; j++) {
                int i = lane + 32 * j;
                int r = r0 + i;
                int b = r / SPX;
                size_t o = ((size_t)(b * DIM + n0 + c)) * SPX + (r - b * SPX);
                out[o] = stg[i * 129 + c] + xres[o];
            }
        }
        return;
    }

    const int mw = r0 + warp_m * 64;
    const int nw = warp_n * 32;
    __half* dp_base = (__half*)dstv;
#pragma unroll
    for (int mf = 0; mf < 4; mf++) {
#pragma unroll
        for (int nf = 0; nf < 4; nf++) {
#pragma unroll
            for (int half = 0; half < 2; half++) {
                int grow = mw + mf * 16 + (lane >> 2) + half * 8;
                int lcol = nw + nf * 8 + (lane & 3) * 2;
                float v0 = fmaf(acc[mf][nf][half * 2 + 0], s_scale[lcol], s_shift[lcol]);
                float v1 = fmaf(acc[mf][nf][half * 2 + 1], s_scale[lcol + 1], s_shift[lcol + 1]);
                if (MODE == 1) {
                    v0 = 0.5f * v0 * (1.0f + erff(v0 * 0.70710678118654752f));
                    v1 = 0.5f * v1 * (1.0f + erff(v1 * 0.70710678118654752f));
                }
                __half2 hp;
                hp.x = __float2half_rn(v0);
                hp.y = __float2half_rn(v1);
                *(__half2*)(dp_base + (size_t)grow * DIM2 + n0 + lcol) = hp;
            }
        }
    }
}

// ---------------------------------------------------------------------------
extern "C" void kernel_launch(void* const* d_in, const int* in_sizes, int n_in,
                              void* d_out, int out_size) {
    const float* x   = (const float*)d_in[0];
    const float* w1  = (const float*)d_in[1];
    const float* b1  = (const float*)d_in[2];
    const float* g1  = (const float*)d_in[3];
    const float* be1 = (const float*)d_in[4];
    const float* m1  = (const float*)d_in[5];
    const float* v1  = (const float*)d_in[6];
    const float* wg  = (const float*)d_in[7];
    const float* bg  = (const float*)d_in[8];
    const float* gg  = (const float*)d_in[9];
    const float* beg = (const float*)d_in[10];
    const float* mg  = (const float*)d_in[11];
    const float* vg  = (const float*)d_in[12];
    const float* w2  = (const float*)d_in[13];
    const float* b2  = (const float*)d_in[14];
    const float* g2  = (const float*)d_in[15];
    const float* be2 = (const float*)d_in[16];
    const float* m2  = (const float*)d_in[17];
    const float* v2  = (const float*)d_in[18];

    __half *xTh, *cath, *gh, *w1h, *wgh, *w2h;
    float *sc1, *sh1, *scg, *shg, *sc2, *sh2;
    cudaGetSymbolAddress((void**)&xTh, g_xTh);
    cudaGetSymbolAddress((void**)&cath, g_cath);
    cudaGetSymbolAddress((void**)&gh, g_gh);
    cudaGetSymbolAddress((void**)&w1h, g_w1h);
    cudaGetSymbolAddress((void**)&wgh, g_wgh);
    cudaGetSymbolAddress((void**)&w2h, g_w2h);
    cudaGetSymbolAddress((void**)&sc1, g_sc1);
    cudaGetSymbolAddress((void**)&sh1, g_sh1);
    cudaGetSymbolAddress((void**)&scg, g_scg);
    cudaGetSymbolAddress((void**)&shg, g_shg);
    cudaGetSymbolAddress((void**)&sc2, g_sc2);
    cudaGetSymbolAddress((void**)&sh2, g_sh2);

    cudaFuncSetAttribute(fp16_gemm<0>, cudaFuncAttributeMaxDynamicSharedMemorySize, GSMEM);
    cudaFuncSetAttribute(fp16_gemm<1>, cudaFuncAttributeMaxDynamicSharedMemorySize, GSMEM);
    cudaFuncSetAttribute(fp16_gemm<2>, cudaFuncAttributeMaxDynamicSharedMemorySize, GSMEM);

    prep_pack<<<1793, 256>>>(w1, wg, w2, b1, g1, be1, m1, v1,
                             bg, gg, beg, mg, vg, b2, g2, be2, m2, v2);
    transpose_in_pack<<<dim3(98, 8, 8), 256>>>(x);

    // fc1: cat[:, 0:256] = fp16(BN(x @ w1^T))
    fp16_gemm<0><<<dim3(196, 2), 256, GSMEM>>>(xTh, w1h, cath, nullptr, sc1, sh1, DIM);
    // MRConv4d -> cat[:, 256:512]
    colmin_kernel<<<dim3(56, 8), 256>>>();
    row_combine_kernel<<<dim3(56, 8), 256>>>();
    // g = fp16(GELU(BN(cat @ wg^T)))
    fp16_gemm<1><<<dim3(196, 4), 256, GSMEM>>>(cath, wgh, gh, nullptr, scg, shg, DIM2);
    // out[B,256,S] = BN(g @ w2^T)^T + x  (fused transpose + residual)
    fp16_gemm<2><<<dim3(196, 2), 256, GSMEM>>>(gh, w2h, d_out, x, sc2, sh2, DIM2);
}